// round 4
// baseline (speedup 1.0000x reference)
#include <cuda_runtime.h>
#include <cuda_bf16.h>
#include <mma.h>

using namespace nvcuda;

#define T_    128
#define B_    256
#define D_    1024
#define H_    1024
#define V_    32000
#define TAGS_ 1024
#define GQ    32      // 4 gates * 8 qubits

// ---------------- scratch (static device globals; no cudaMalloc allowed) ----
__device__ float          g_embproj[V_ * GQ];           // emb @ Wg_x  (4.1 MB)
__device__ __nv_bfloat16  g_lstm[(size_t)T_ * B_ * H_]; // lstm_out bf16 (64 MB)
__device__ __nv_bfloat16  g_wtag[H_ * TAGS_];           // W_tag bf16 (2 MB)

// ---------------- helpers ----------------------------------------------------
__device__ __forceinline__ void cp16(void* smem, const void* gmem) {
    unsigned sa = (unsigned)__cvta_generic_to_shared(smem);
    asm volatile("cp.async.cg.shared.global [%0], [%1], 16;\n" :: "r"(sa), "l"(gmem));
}
__device__ __forceinline__ float fast_sigmoid(float x) {
    return 0.5f + 0.5f * __tanhf(0.5f * x);
}

// ---------------- K0: W_tag -> bf16 -----------------------------------------
__global__ void wtag_convert(const float* __restrict__ w) {
    int i = blockIdx.x * 256 + threadIdx.x;
    g_wtag[i] = __float2bfloat16(w[i]);
}

// ---------------- K1: embproj = emb @ Wg[:, :D, :]  (32000 x 32) ------------
__global__ __launch_bounds__(256) void embproj_kernel(const float* __restrict__ emb,
                                                      const float* __restrict__ Wg) {
    __shared__ float As[128][33];
    __shared__ __align__(16) float Bs[32][36];
    int tid = threadIdx.x;
    int v0  = blockIdx.x * 128;
    int tr  = tid >> 3;
    int tc  = tid & 7;
    float acc[4][4] = {};

    for (int k0 = 0; k0 < D_; k0 += 32) {
        #pragma unroll
        for (int i = 0; i < 4; i++) {
            int f4  = tid + i * 256;
            int row = f4 >> 3;
            int c4  = (f4 & 7) * 4;
            float4 a = *(const float4*)&emb[(size_t)(v0 + row) * D_ + k0 + c4];
            As[row][c4 + 0] = a.x; As[row][c4 + 1] = a.y;
            As[row][c4 + 2] = a.z; As[row][c4 + 3] = a.w;
        }
        #pragma unroll
        for (int i = 0; i < 4; i++) {
            int idx = tid + i * 256;
            int k = idx >> 5, gq = idx & 31;
            int g = gq >> 3,  q  = gq & 7;
            Bs[k][gq] = Wg[g * (2048 * 8) + (k0 + k) * 8 + q];
        }
        __syncthreads();
        #pragma unroll
        for (int k = 0; k < 32; k++) {
            float4 b4 = *(const float4*)&Bs[k][tc * 4];
            #pragma unroll
            for (int i = 0; i < 4; i++) {
                float a = As[tr * 4 + i][k];
                acc[i][0] += a * b4.x; acc[i][1] += a * b4.y;
                acc[i][2] += a * b4.z; acc[i][3] += a * b4.w;
            }
        }
        __syncthreads();
    }
    #pragma unroll
    for (int i = 0; i < 4; i++) {
        float4 o = make_float4(acc[i][0], acc[i][1], acc[i][2], acc[i][3]);
        *(float4*)&g_embproj[(v0 + tr * 4 + i) * GQ + tc * 4] = o;
    }
}

// ---------------- K2: LSTM recurrence, one block per TWO batch elements -----
// smem floats: W2[1024][33] | xq0[128*32] | xq1 | qcos0[32] | qcos1[32]
//              | red0[32*33] | red1[32*33]
#define LSTM_SMEM ((1024 * 33 + 2 * 4096 + 2 * 32 + 2 * 32 * 33) * 4)

__global__ __launch_bounds__(1024, 1) void lstm_kernel(
    const int*   __restrict__ sentence,
    const float* __restrict__ Wg,
    const float* __restrict__ bg,
    const float* __restrict__ theta,
    const float* __restrict__ Wp,
    const float* __restrict__ bp) {
    extern __shared__ float sm[];
    float* W2    = sm;                      // 1024*33
    float* xq0   = sm + 1024 * 33;          // 4096
    float* xq1   = xq0 + 4096;              // 4096
    float* qcos0 = xq1 + 4096;              // 32 (16B aligned)
    float* qcos1 = qcos0 + 32;              // 32
    float* red0  = qcos1 + 32;              // 32*33
    float* red1  = red0 + 32 * 33;          // 32*33

    const int tid  = threadIdx.x;           // hidden unit j
    const int warp = tid >> 5;
    const int lane = tid & 31;
    const int b0   = blockIdx.x * 2;

    // transposed hidden weights: W2[j][gq] = Wg[g][D + j][q]
    #pragma unroll
    for (int it = 0; it < 4; it++) {
        int p = tid + it * 1024;
        int g = p >> 10, j = p & 1023;
        const float* src = Wg + g * (2048 * 8) + (1024 + j) * 8;
        float4 v0 = *(const float4*)src;
        float4 v1 = *(const float4*)(src + 4);
        float* dst = W2 + j * 33 + g * 8;
        dst[0] = v0.x; dst[1] = v0.y; dst[2] = v0.z; dst[3] = v0.w;
        dst[4] = v1.x; dst[5] = v1.y; dst[6] = v1.z; dst[7] = v1.w;
    }
    // xq[b][t][gq] = embproj[token][gq] + bg[gq] + theta[gq]
    #pragma unroll
    for (int it = 0; it < 8; it++) {
        int p  = tid + it * 1024;
        int bb = p >> 12;
        int r  = p & 4095;
        int t  = r >> 5, gq = r & 31;
        int token = sentence[t * B_ + b0 + bb];
        float v = g_embproj[token * GQ + gq] + bg[gq] + theta[gq];
        (bb ? xq1 : xq0)[t * 32 + gq] = v;
    }
    float wpreg[32];
    #pragma unroll
    for (int gq = 0; gq < 32; gq++) wpreg[gq] = Wp[gq * H_ + tid];
    float bp4[4];
    #pragma unroll
    for (int g = 0; g < 4; g++) bp4[g] = bp[g * H_ + tid];

    float h0 = 0.f, h1 = 0.f, c0 = 0.f, c1 = 0.f;
    __syncthreads();

    for (int t = 0; t < T_; t++) {
        // matvec: warp w covers j in [32w, 32w+32), lane = gq. h lives in regs.
        float s0 = 0.f, s1 = 0.f;
        const float* wrow = W2 + (warp * 32) * 33 + lane;
        #pragma unroll
        for (int j = 0; j < 32; j++) {
            float wv = wrow[j * 33];
            s0 = fmaf(__shfl_sync(0xffffffffu, h0, j), wv, s0);
            s1 = fmaf(__shfl_sync(0xffffffffu, h1, j), wv, s1);
        }
        red0[warp * 33 + lane] = s0;
        red1[warp * 33 + lane] = s1;
        __syncthreads();
        if (warp < 2) {
            const float* rd = warp ? red1 : red0;
            float tt = 0.f;
            #pragma unroll
            for (int wi = 0; wi < 32; wi++) tt += rd[wi * 33 + lane];
            float x = (warp ? xq1 : xq0)[t * 32 + lane];
            (warp ? qcos1 : qcos0)[lane] = __cosf(tt + x);
        }
        __syncthreads();

        // gates for both batch elements
        const float4* qa0 = (const float4*)qcos0;
        const float4* qa1 = (const float4*)qcos1;
        float pj0[4], pj1[4];
        #pragma unroll
        for (int g = 0; g < 4; g++) {
            float4 xa = qa0[2 * g], ya = qa0[2 * g + 1];
            float a = bp4[g];
            a = fmaf(xa.x, wpreg[g * 8 + 0], a); a = fmaf(xa.y, wpreg[g * 8 + 1], a);
            a = fmaf(xa.z, wpreg[g * 8 + 2], a); a = fmaf(xa.w, wpreg[g * 8 + 3], a);
            a = fmaf(ya.x, wpreg[g * 8 + 4], a); a = fmaf(ya.y, wpreg[g * 8 + 5], a);
            a = fmaf(ya.z, wpreg[g * 8 + 6], a); a = fmaf(ya.w, wpreg[g * 8 + 7], a);
            pj0[g] = a;
            float4 xb = qa1[2 * g], yb = qa1[2 * g + 1];
            float b = bp4[g];
            b = fmaf(xb.x, wpreg[g * 8 + 0], b); b = fmaf(xb.y, wpreg[g * 8 + 1], b);
            b = fmaf(xb.z, wpreg[g * 8 + 2], b); b = fmaf(xb.w, wpreg[g * 8 + 3], b);
            b = fmaf(yb.x, wpreg[g * 8 + 4], b); b = fmaf(yb.y, wpreg[g * 8 + 5], b);
            b = fmaf(yb.z, wpreg[g * 8 + 6], b); b = fmaf(yb.w, wpreg[g * 8 + 7], b);
            pj1[g] = b;
        }
        float fg = fast_sigmoid(pj0[0]);
        float ig = fast_sigmoid(pj0[1]);
        float gg = __tanhf(pj0[2]);
        float og = fast_sigmoid(pj0[3]);
        c0 = fg * c0 + ig * gg;
        h0 = og * __tanhf(c0);

        fg = fast_sigmoid(pj1[0]);
        ig = fast_sigmoid(pj1[1]);
        gg = __tanhf(pj1[2]);
        og = fast_sigmoid(pj1[3]);
        c1 = fg * c1 + ig * gg;
        h1 = og * __tanhf(c1);

        size_t base = ((size_t)t * B_ + b0) * H_ + tid;
        g_lstm[base]      = __float2bfloat16(h0);
        g_lstm[base + H_] = __float2bfloat16(h1);
    }
}

// ---------------- K3: fused tag GEMM (bf16 WMMA, cp.async pipelined) --------
// block = one (t, 128-tag chunk): tile 256(b) x 128(tags), K = 1024, KT = 64,
// 2-stage cp.async double buffer. b_tag cancels in batch-axis log_softmax.
#define A_STG (256 * 72)     // halves per A stage (ld = 72)
#define B_STG (64 * 136)     // halves per B stage (ld = 136)
#define TAG_SMEM (256 * 136 * 4 + 512 * 4)   // epilogue tile dominates (aliases)

__global__ __launch_bounds__(512, 1) void tag_kernel(float* __restrict__ out) {
    extern __shared__ char smraw[];
    __nv_bfloat16* Asm = (__nv_bfloat16*)smraw;   // 2 stages 256x72
    __nv_bfloat16* Bsm = Asm + 2 * A_STG;         // 2 stages 64x136
    float* Osm = (float*)smraw;                   // 256 x 136 fp32 (alias)
    float* red = Osm + 256 * 136;

    const int tid = threadIdx.x;
    const int t   = blockIdx.y;
    const int c0  = blockIdx.x * 128;
    const int w   = tid >> 5;
    const int wy  = w >> 2;
    const int wx  = w & 3;

    wmma::fragment<wmma::accumulator, 16, 16, 16, float> acc[4][2];
    #pragma unroll
    for (int i = 0; i < 4; i++)
        #pragma unroll
        for (int j = 0; j < 2; j++) wmma::fill_fragment(acc[i][j], 0.f);

    auto issue_tile = [&](int kt) {
        int s  = kt & 1;
        int k0 = kt * 64;
        __nv_bfloat16* As = Asm + s * A_STG;
        __nv_bfloat16* Bs = Bsm + s * B_STG;
        #pragma unroll
        for (int i = 0; i < 4; i++) {
            int e = tid + i * 512;
            int row = e >> 3, c8 = (e & 7) * 8;
            cp16(&As[row * 72 + c8],
                 &g_lstm[((size_t)t * B_ + row) * H_ + k0 + c8]);
        }
        #pragma unroll
        for (int i = 0; i < 2; i++) {
            int e = tid + i * 512;
            int row = e >> 4, c8 = (e & 15) * 8;
            cp16(&Bs[row * 136 + c8],
                 &g_wtag[(size_t)(k0 + row) * TAGS_ + c0 + c8]);
        }
        asm volatile("cp.async.commit_group;\n" ::);
    };

    issue_tile(0);
    for (int kt = 0; kt < 16; kt++) {
        if (kt + 1 < 16) {
            issue_tile(kt + 1);
            asm volatile("cp.async.wait_group 1;\n" ::);
        } else {
            asm volatile("cp.async.wait_group 0;\n" ::);
        }
        __syncthreads();
        int s = kt & 1;
        const __nv_bfloat16* As = Asm + s * A_STG;
        const __nv_bfloat16* Bs = Bsm + s * B_STG;
        #pragma unroll
        for (int ks = 0; ks < 64; ks += 16) {
            wmma::fragment<wmma::matrix_a, 16, 16, 16, __nv_bfloat16, wmma::row_major> af[4];
            wmma::fragment<wmma::matrix_b, 16, 16, 16, __nv_bfloat16, wmma::row_major> bf[2];
            #pragma unroll
            for (int i = 0; i < 4; i++)
                wmma::load_matrix_sync(af[i], &As[(wy * 64 + i * 16) * 72 + ks], 72);
            #pragma unroll
            for (int j = 0; j < 2; j++)
                wmma::load_matrix_sync(bf[j], &Bs[ks * 136 + wx * 32 + j * 16], 136);
            #pragma unroll
            for (int i = 0; i < 4; i++)
                #pragma unroll
                for (int j = 0; j < 2; j++)
                    wmma::mma_sync(acc[i][j], af[i], bf[j], acc[i][j]);
        }
        __syncthreads();
    }

    // spill accumulators to smem tile (aliases stage buffers; final sync above)
    #pragma unroll
    for (int i = 0; i < 4; i++)
        #pragma unroll
        for (int j = 0; j < 2; j++)
            wmma::store_matrix_sync(&Osm[(wy * 64 + i * 16) * 136 + wx * 32 + j * 16],
                                    acc[i][j], 136, wmma::mem_row_major);
    __syncthreads();

    // log_softmax over the 256 rows (batch) per column (tag)
    const int p = tid >> 7;
    const int c = tid & 127;
    float m = -1e30f;
    #pragma unroll 8
    for (int i = 0; i < 64; i++) m = fmaxf(m, Osm[(p * 64 + i) * 136 + c]);
    red[p * 128 + c] = m;
    __syncthreads();
    float M = fmaxf(fmaxf(red[c], red[128 + c]), fmaxf(red[256 + c], red[384 + c]));
    float ssum = 0.f;
    #pragma unroll 8
    for (int i = 0; i < 64; i++) ssum += __expf(Osm[(p * 64 + i) * 136 + c] - M);
    __syncthreads();
    red[p * 128 + c] = ssum;
    __syncthreads();
    float lse = M + logf(red[c] + red[128 + c] + red[256 + c] + red[384 + c]);
    #pragma unroll 8
    for (int i = 0; i < 64; i++) {
        int b = p * 64 + i;
        out[((size_t)t * B_ + b) * TAGS_ + c0 + c] = Osm[b * 136 + c] - lse;
    }
}

// ---------------- launch -----------------------------------------------------
extern "C" void kernel_launch(void* const* d_in, const int* in_sizes, int n_in,
                              void* d_out, int out_size) {
    const int*   sentence = (const int*)  d_in[0];
    const float* emb      = (const float*)d_in[1];
    const float* Wg       = (const float*)d_in[2];
    const float* bg       = (const float*)d_in[3];
    const float* theta    = (const float*)d_in[4];
    const float* Wp       = (const float*)d_in[5];
    const float* bp       = (const float*)d_in[6];
    const float* W_tag    = (const float*)d_in[7];
    // d_in[8] = b_tag: cancels in log_softmax over batch axis -> unused
    float* out = (float*)d_out;

    cudaFuncSetAttribute(lstm_kernel, cudaFuncAttributeMaxDynamicSharedMemorySize, LSTM_SMEM);
    cudaFuncSetAttribute(tag_kernel,  cudaFuncAttributeMaxDynamicSharedMemorySize, TAG_SMEM);

    wtag_convert<<<(H_ * TAGS_) / 256, 256>>>(W_tag);
    embproj_kernel<<<V_ / 128, 256>>>(emb, Wg);
    lstm_kernel<<<B_ / 2, 1024, LSTM_SMEM>>>(sentence, Wg, bg, theta, Wp, bp);
    dim3 g3(TAGS_ / 128, T_);
    tag_kernel<<<g3, 512, TAG_SMEM>>>(out);
}

// round 6
// speedup vs baseline: 1.0079x; 1.0079x over previous
#include <cuda_runtime.h>
#include <cuda_bf16.h>
#include <mma.h>

using namespace nvcuda;

#define T_    128
#define B_    256
#define D_    1024
#define H_    1024
#define V_    32000
#define TAGS_ 1024
#define GQ    32      // 4 gates * 8 qubits

// ---------------- scratch (static device globals; no cudaMalloc allowed) ----
__device__ float          g_embproj[V_ * GQ];           // emb @ Wg_x
__device__ __nv_bfloat16  g_lstm[(size_t)T_ * B_ * H_]; // lstm_out bf16
__device__ __nv_bfloat16  g_wtag[H_ * TAGS_];           // W_tag bf16

// ---------------- helpers ----------------------------------------------------
__device__ __forceinline__ void cp16(void* smem, const void* gmem) {
    unsigned sa = (unsigned)__cvta_generic_to_shared(smem);
    asm volatile("cp.async.cg.shared.global [%0], [%1], 16;\n" :: "r"(sa), "l"(gmem));
}
__device__ __forceinline__ float fast_sigmoid(float x) {
    return 0.5f + 0.5f * __tanhf(0.5f * x);
}

// ---------------- K0: W_tag -> bf16 -----------------------------------------
__global__ void wtag_convert(const float* __restrict__ w) {
    int i = blockIdx.x * 256 + threadIdx.x;
    g_wtag[i] = __float2bfloat16(w[i]);
}

// ---------------- K1: embproj = emb @ Wg[:, :D, :]  (32000 x 32) ------------
__global__ __launch_bounds__(256) void embproj_kernel(const float* __restrict__ emb,
                                                      const float* __restrict__ Wg) {
    __shared__ float As[128][33];
    __shared__ __align__(16) float Bs[32][36];
    int tid = threadIdx.x;
    int v0  = blockIdx.x * 128;
    int tr  = tid >> 3, tc = tid & 7;
    float acc[4][4] = {};

    for (int k0 = 0; k0 < D_; k0 += 32) {
        #pragma unroll
        for (int i = 0; i < 4; i++) {
            int f4  = tid + i * 256;
            int row = f4 >> 3, c4 = (f4 & 7) * 4;
            float4 a = *(const float4*)&emb[(size_t)(v0 + row) * D_ + k0 + c4];
            As[row][c4] = a.x; As[row][c4 + 1] = a.y;
            As[row][c4 + 2] = a.z; As[row][c4 + 3] = a.w;
        }
        #pragma unroll
        for (int i = 0; i < 4; i++) {
            int idx = tid + i * 256;
            int k = idx >> 5, gq = idx & 31;
            Bs[k][gq] = Wg[(gq >> 3) * (2048 * 8) + (k0 + k) * 8 + (gq & 7)];
        }
        __syncthreads();
        #pragma unroll
        for (int k = 0; k < 32; k++) {
            float4 b4 = *(const float4*)&Bs[k][tc * 4];
            #pragma unroll
            for (int i = 0; i < 4; i++) {
                float a = As[tr * 4 + i][k];
                acc[i][0] += a * b4.x; acc[i][1] += a * b4.y;
                acc[i][2] += a * b4.z; acc[i][3] += a * b4.w;
            }
        }
        __syncthreads();
    }
    #pragma unroll
    for (int i = 0; i < 4; i++) {
        float4 o = make_float4(acc[i][0], acc[i][1], acc[i][2], acc[i][3]);
        *(float4*)&g_embproj[(v0 + tr * 4 + i) * GQ + tc * 4] = o;
    }
}

// ---------------- K2: LSTM, 512 thr/CTA, 2 hidden units/thread, 2 batch/CTA --
// smem floats: W2[1024][33] fp32 | xq0[4096] | xq1[4096] | qcos0[32] | qcos1[32]
//              | red0[16*33] | red1[16*33]   => 172.4 KB
#define LSTM_SMEM ((1024 * 33 + 2 * 4096 + 2 * 32 + 2 * 16 * 33) * 4)

__device__ __forceinline__ void gate_update(const float4* qc, const float* wp,
                                            const float* bpv, float& c, float& h) {
    float pj[4];
    #pragma unroll
    for (int g = 0; g < 4; g++) {
        float4 a = qc[2 * g], b = qc[2 * g + 1];
        float s = bpv[g];
        s = fmaf(a.x, wp[g * 8 + 0], s); s = fmaf(a.y, wp[g * 8 + 1], s);
        s = fmaf(a.z, wp[g * 8 + 2], s); s = fmaf(a.w, wp[g * 8 + 3], s);
        s = fmaf(b.x, wp[g * 8 + 4], s); s = fmaf(b.y, wp[g * 8 + 5], s);
        s = fmaf(b.z, wp[g * 8 + 6], s); s = fmaf(b.w, wp[g * 8 + 7], s);
        pj[g] = s;
    }
    float fg = fast_sigmoid(pj[0]);
    float ig = fast_sigmoid(pj[1]);
    float gg = __tanhf(pj[2]);
    float og = fast_sigmoid(pj[3]);
    c = fg * c + ig * gg;
    h = og * __tanhf(c);
}

__global__ __launch_bounds__(512, 1) void lstm_kernel(
    const int*   __restrict__ sentence,
    const float* __restrict__ Wg,
    const float* __restrict__ bg,
    const float* __restrict__ theta,
    const float* __restrict__ Wp,
    const float* __restrict__ bp) {
    extern __shared__ float sm[];
    float* W2    = sm;                      // 1024 x 33 (row j, col gq)
    float* xq0   = sm + 1024 * 33;          // 4096
    float* xq1   = xq0 + 4096;              // 4096
    float* qcos0 = xq1 + 4096;              // 32 (16B aligned)
    float* qcos1 = qcos0 + 32;              // 32
    float* red0  = qcos1 + 32;              // 16 x 33
    float* red1  = red0 + 16 * 33;          // 16 x 33

    const int tid  = threadIdx.x;
    const int warp = tid >> 5, lane = tid & 31;
    const int b0   = blockIdx.x * 2;

    // W2[j][gq] = Wg[g][D + j][q]   (4096 (g,j) pairs, 8 per thread)
    #pragma unroll
    for (int it = 0; it < 8; it++) {
        int p = tid + it * 512;
        int g = p >> 10, j = p & 1023;
        const float* src = Wg + g * (2048 * 8) + (size_t)(1024 + j) * 8;
        float4 v0 = *(const float4*)src;
        float4 v1 = *(const float4*)(src + 4);
        float* dst = W2 + j * 33 + g * 8;
        dst[0] = v0.x; dst[1] = v0.y; dst[2] = v0.z; dst[3] = v0.w;
        dst[4] = v1.x; dst[5] = v1.y; dst[6] = v1.z; dst[7] = v1.w;
    }
    // xq[b][t][gq] = embproj[token][gq] + bg[gq] + theta[gq]
    #pragma unroll
    for (int it = 0; it < 16; it++) {
        int p  = tid + it * 512;             // 8192 total
        int bb = p >> 12, r = p & 4095;
        int t  = r >> 5, gq = r & 31;
        int token = sentence[t * B_ + b0 + bb];
        (bb ? xq1 : xq0)[t * 32 + gq] =
            g_embproj[token * GQ + gq] + bg[gq] + theta[gq];
    }
    // per-thread Wp slices for j = tid and j = tid + 512
    float wpreg[64], bpv[8];
    #pragma unroll
    for (int k = 0; k < 32; k++) {
        wpreg[k]      = Wp[k * H_ + tid];
        wpreg[32 + k] = Wp[k * H_ + tid + 512];
    }
    #pragma unroll
    for (int g = 0; g < 4; g++) {
        bpv[g]     = bp[g * H_ + tid];
        bpv[4 + g] = bp[g * H_ + tid + 512];
    }

    // h/c state: (batch 0|1) x (j = tid | j = tid+512)
    float h0a = 0.f, h0b = 0.f, h1a = 0.f, h1b = 0.f;
    float c0a = 0.f, c0b = 0.f, c1a = 0.f, c1b = 0.f;
    __syncthreads();

    const int rgq = 2 * warp + (lane >> 4);  // gq reduced by this half-warp
    const int ri  = lane & 15;               // partial index within reduction

    for (int t = 0; t < T_; t++) {
        // partial matvec: warp w covers j in [32w,32w+32) and [512+32w, ...)
        // lane = gq; h values shuffled from this warp's own registers.
        float s0 = 0.f, s1 = 0.f;
        {
            const float* w1p = W2 + (32 * warp) * 33 + lane;
            const float* w2p = W2 + (512 + 32 * warp) * 33 + lane;
            #pragma unroll
            for (int jj = 0; jj < 32; jj++) {
                float w1 = w1p[jj * 33];
                float w2 = w2p[jj * 33];
                float a0 = __shfl_sync(~0u, h0a, jj);
                float a1 = __shfl_sync(~0u, h1a, jj);
                float b0f = __shfl_sync(~0u, h0b, jj);
                float b1f = __shfl_sync(~0u, h1b, jj);
                s0 = fmaf(a0, w1, s0); s0 = fmaf(b0f, w2, s0);
                s1 = fmaf(a1, w1, s1); s1 = fmaf(b1f, w2, s1);
            }
        }
        red0[warp * 33 + lane] = s0;
        red1[warp * 33 + lane] = s1;
        __syncthreads();
        {
            // half-warp (16 lanes) reduces 16 partials for gq = rgq
            float v0 = red0[ri * 33 + rgq];
            float v1 = red1[ri * 33 + rgq];
            #pragma unroll
            for (int off = 8; off > 0; off >>= 1) {
                v0 += __shfl_xor_sync(~0u, v0, off);
                v1 += __shfl_xor_sync(~0u, v1, off);
            }
            if (ri == 0) {
                qcos0[rgq] = __cosf(v0 + xq0[t * 32 + rgq]);
                qcos1[rgq] = __cosf(v1 + xq1[t * 32 + rgq]);
            }
        }
        __syncthreads();

        const float4* q0 = (const float4*)qcos0;
        const float4* q1 = (const float4*)qcos1;
        gate_update(q0, wpreg,      bpv,     c0a, h0a);
        gate_update(q0, wpreg + 32, bpv + 4, c0b, h0b);
        gate_update(q1, wpreg,      bpv,     c1a, h1a);
        gate_update(q1, wpreg + 32, bpv + 4, c1b, h1b);

        size_t base = ((size_t)t * B_ + b0) * H_;
        g_lstm[base + tid]            = __float2bfloat16(h0a);
        g_lstm[base + tid + 512]      = __float2bfloat16(h0b);
        g_lstm[base + H_ + tid]       = __float2bfloat16(h1a);
        g_lstm[base + H_ + tid + 512] = __float2bfloat16(h1b);
    }
}

// ---------------- K3: fused tag GEMM (bf16 WMMA, cp.async pipelined) --------
// block = one (t, 128-tag chunk): tile 256(b) x 128(tags), K = 1024, KT = 64,
// 2-stage cp.async double buffer. b_tag cancels in batch-axis log_softmax.
#define A_STG (256 * 72)     // halves per A stage (ld = 72)
#define B_STG (64 * 136)     // halves per B stage (ld = 136)
#define TAG_SMEM (256 * 136 * 4 + 512 * 4)   // epilogue tile dominates (aliases)

__global__ __launch_bounds__(512, 1) void tag_kernel(float* __restrict__ out) {
    extern __shared__ char smraw[];
    __nv_bfloat16* Asm = (__nv_bfloat16*)smraw;   // 2 stages 256x72
    __nv_bfloat16* Bsm = Asm + 2 * A_STG;         // 2 stages 64x136
    float* Osm = (float*)smraw;                   // 256 x 136 fp32 (alias)
    float* red = Osm + 256 * 136;

    const int tid = threadIdx.x;
    const int t   = blockIdx.y;
    const int c0  = blockIdx.x * 128;
    const int w   = tid >> 5;
    const int wy  = w >> 2;
    const int wx  = w & 3;

    wmma::fragment<wmma::accumulator, 16, 16, 16, float> acc[4][2];
    #pragma unroll
    for (int i = 0; i < 4; i++)
        #pragma unroll
        for (int j = 0; j < 2; j++) wmma::fill_fragment(acc[i][j], 0.f);

    auto issue_tile = [&](int kt) {
        int s  = kt & 1;
        int k0 = kt * 64;
        __nv_bfloat16* As = Asm + s * A_STG;
        __nv_bfloat16* Bs = Bsm + s * B_STG;
        #pragma unroll
        for (int i = 0; i < 4; i++) {
            int e = tid + i * 512;
            int row = e >> 3, c8 = (e & 7) * 8;
            cp16(&As[row * 72 + c8],
                 &g_lstm[((size_t)t * B_ + row) * H_ + k0 + c8]);
        }
        #pragma unroll
        for (int i = 0; i < 2; i++) {
            int e = tid + i * 512;
            int row = e >> 4, c8 = (e & 15) * 8;
            cp16(&Bs[row * 136 + c8],
                 &g_wtag[(size_t)(k0 + row) * TAGS_ + c0 + c8]);
        }
        asm volatile("cp.async.commit_group;\n" ::);
    };

    issue_tile(0);
    for (int kt = 0; kt < 16; kt++) {
        if (kt + 1 < 16) {
            issue_tile(kt + 1);
            asm volatile("cp.async.wait_group 1;\n" ::);
        } else {
            asm volatile("cp.async.wait_group 0;\n" ::);
        }
        __syncthreads();
        int s = kt & 1;
        const __nv_bfloat16* As = Asm + s * A_STG;
        const __nv_bfloat16* Bs = Bsm + s * B_STG;
        #pragma unroll
        for (int ks = 0; ks < 64; ks += 16) {
            wmma::fragment<wmma::matrix_a, 16, 16, 16, __nv_bfloat16, wmma::row_major> af[4];
            wmma::fragment<wmma::matrix_b, 16, 16, 16, __nv_bfloat16, wmma::row_major> bf[2];
            #pragma unroll
            for (int i = 0; i < 4; i++)
                wmma::load_matrix_sync(af[i], &As[(wy * 64 + i * 16) * 72 + ks], 72);
            #pragma unroll
            for (int j = 0; j < 2; j++)
                wmma::load_matrix_sync(bf[j], &Bs[ks * 136 + wx * 32 + j * 16], 136);
            #pragma unroll
            for (int i = 0; i < 4; i++)
                #pragma unroll
                for (int j = 0; j < 2; j++)
                    wmma::mma_sync(acc[i][j], af[i], bf[j], acc[i][j]);
        }
        __syncthreads();
    }

    // spill accumulators to smem tile (aliases stage buffers; final sync above)
    #pragma unroll
    for (int i = 0; i < 4; i++)
        #pragma unroll
        for (int j = 0; j < 2; j++)
            wmma::store_matrix_sync(&Osm[(wy * 64 + i * 16) * 136 + wx * 32 + j * 16],
                                    acc[i][j], 136, wmma::mem_row_major);
    __syncthreads();

    // log_softmax over the 256 rows (batch) per column (tag)
    const int p = tid >> 7;
    const int c = tid & 127;
    float m = -1e30f;
    #pragma unroll 8
    for (int i = 0; i < 64; i++) m = fmaxf(m, Osm[(p * 64 + i) * 136 + c]);
    red[p * 128 + c] = m;
    __syncthreads();
    float M = fmaxf(fmaxf(red[c], red[128 + c]), fmaxf(red[256 + c], red[384 + c]));
    float ssum = 0.f;
    #pragma unroll 8
    for (int i = 0; i < 64; i++) ssum += __expf(Osm[(p * 64 + i) * 136 + c] - M);
    __syncthreads();
    red[p * 128 + c] = ssum;
    __syncthreads();
    float lse = M + logf(red[c] + red[128 + c] + red[256 + c] + red[384 + c]);
    #pragma unroll 8
    for (int i = 0; i < 64; i++) {
        int b = p * 64 + i;
        out[((size_t)t * B_ + b) * TAGS_ + c0 + c] = Osm[b * 136 + c] - lse;
    }
}

// ---------------- launch -----------------------------------------------------
extern "C" void kernel_launch(void* const* d_in, const int* in_sizes, int n_in,
                              void* d_out, int out_size) {
    const int*   sentence = (const int*)  d_in[0];
    const float* emb      = (const float*)d_in[1];
    const float* Wg       = (const float*)d_in[2];
    const float* bg       = (const float*)d_in[3];
    const float* theta    = (const float*)d_in[4];
    const float* Wp       = (const float*)d_in[5];
    const float* bp       = (const float*)d_in[6];
    const float* W_tag    = (const float*)d_in[7];
    // d_in[8] = b_tag: cancels in log_softmax over batch axis -> unused
    float* out = (float*)d_out;

    cudaFuncSetAttribute(lstm_kernel, cudaFuncAttributeMaxDynamicSharedMemorySize, LSTM_SMEM);
    cudaFuncSetAttribute(tag_kernel,  cudaFuncAttributeMaxDynamicSharedMemorySize, TAG_SMEM);

    wtag_convert<<<(H_ * TAGS_) / 256, 256>>>(W_tag);
    embproj_kernel<<<V_ / 128, 256>>>(emb, Wg);
    lstm_kernel<<<B_ / 2, 512, LSTM_SMEM>>>(sentence, Wg, bg, theta, Wp, bp);
    dim3 g3(TAGS_ / 128, T_);
    tag_kernel<<<g3, 512, TAG_SMEM>>>(out);
}

// round 7
// speedup vs baseline: 1.1139x; 1.1052x over previous
#include <cuda_runtime.h>
#include <cuda_bf16.h>
#include <mma.h>

using namespace nvcuda;

#define T_    128
#define B_    256
#define D_    1024
#define H_    1024
#define V_    32000
#define TAGS_ 1024
#define GQ    32      // 4 gates * 8 qubits

// ---------------- scratch (static device globals; no cudaMalloc allowed) ----
__device__ float          g_embproj[V_ * GQ];           // emb @ Wg_x
__device__ __nv_bfloat16  g_lstm[(size_t)T_ * B_ * H_]; // lstm_out bf16
__device__ __nv_bfloat16  g_wtag[H_ * TAGS_];           // W_tag bf16

// ---------------- helpers ----------------------------------------------------
__device__ __forceinline__ void cp16(void* smem, const void* gmem) {
    unsigned sa = (unsigned)__cvta_generic_to_shared(smem);
    asm volatile("cp.async.cg.shared.global [%0], [%1], 16;\n" :: "r"(sa), "l"(gmem));
}
__device__ __forceinline__ float fast_sigmoid(float x) {
    return 0.5f + 0.5f * __tanhf(0.5f * x);
}

// ---------------- K0: W_tag -> bf16 -----------------------------------------
__global__ void wtag_convert(const float* __restrict__ w) {
    int i = blockIdx.x * 256 + threadIdx.x;
    g_wtag[i] = __float2bfloat16(w[i]);
}

// ---------------- K1: embproj = emb @ Wg[:, :D, :]  (32000 x 32) ------------
__global__ __launch_bounds__(256) void embproj_kernel(const float* __restrict__ emb,
                                                      const float* __restrict__ Wg) {
    __shared__ float As[128][33];
    __shared__ __align__(16) float Bs[32][36];
    int tid = threadIdx.x;
    int v0  = blockIdx.x * 128;
    int tr  = tid >> 3, tc = tid & 7;
    float acc[4][4] = {};

    for (int k0 = 0; k0 < D_; k0 += 32) {
        #pragma unroll
        for (int i = 0; i < 4; i++) {
            int f4  = tid + i * 256;
            int row = f4 >> 3, c4 = (f4 & 7) * 4;
            float4 a = *(const float4*)&emb[(size_t)(v0 + row) * D_ + k0 + c4];
            As[row][c4] = a.x; As[row][c4 + 1] = a.y;
            As[row][c4 + 2] = a.z; As[row][c4 + 3] = a.w;
        }
        #pragma unroll
        for (int i = 0; i < 4; i++) {
            int idx = tid + i * 256;
            int k = idx >> 5, gq = idx & 31;
            Bs[k][gq] = Wg[(gq >> 3) * (2048 * 8) + (k0 + k) * 8 + (gq & 7)];
        }
        __syncthreads();
        #pragma unroll
        for (int k = 0; k < 32; k++) {
            float4 b4 = *(const float4*)&Bs[k][tc * 4];
            #pragma unroll
            for (int i = 0; i < 4; i++) {
                float a = As[tr * 4 + i][k];
                acc[i][0] += a * b4.x; acc[i][1] += a * b4.y;
                acc[i][2] += a * b4.z; acc[i][3] += a * b4.w;
            }
        }
        __syncthreads();
    }
    #pragma unroll
    for (int i = 0; i < 4; i++) {
        float4 o = make_float4(acc[i][0], acc[i][1], acc[i][2], acc[i][3]);
        *(float4*)&g_embproj[(v0 + tr * 4 + i) * GQ + tc * 4] = o;
    }
}

// ---------------- K2: LSTM, k-parallel matvec (no shfl in hot loop) ----------
// 512 thr/CTA, 2 hidden units/thread, 2 batch/CTA, 128 CTAs (1 wave).
// smem: Wk[32][1028] fp32 k-major | h0s[1024] | h1s[1024] | xq0/1[4096] | qc0/1[32]
#define LSTM_SMEM ((32 * 1028 + 2 * 1024 + 2 * 4096 + 64) * 4)

__device__ __forceinline__ void gate_update(const float4* qc, const float* wp,
                                            const float* bpv, float& c, float& h) {
    float pj[4];
    #pragma unroll
    for (int g = 0; g < 4; g++) {
        float4 a = qc[2 * g], b = qc[2 * g + 1];
        float s = bpv[g];
        s = fmaf(a.x, wp[g * 8 + 0], s); s = fmaf(a.y, wp[g * 8 + 1], s);
        s = fmaf(a.z, wp[g * 8 + 2], s); s = fmaf(a.w, wp[g * 8 + 3], s);
        s = fmaf(b.x, wp[g * 8 + 4], s); s = fmaf(b.y, wp[g * 8 + 5], s);
        s = fmaf(b.z, wp[g * 8 + 6], s); s = fmaf(b.w, wp[g * 8 + 7], s);
        pj[g] = s;
    }
    float fg = fast_sigmoid(pj[0]);
    float ig = fast_sigmoid(pj[1]);
    float gg = __tanhf(pj[2]);
    float og = fast_sigmoid(pj[3]);
    c = fg * c + ig * gg;
    h = og * __tanhf(c);
}

__global__ __launch_bounds__(512, 1) void lstm_kernel(
    const int*   __restrict__ sentence,
    const float* __restrict__ Wg,
    const float* __restrict__ bg,
    const float* __restrict__ theta,
    const float* __restrict__ Wp,
    const float* __restrict__ bp) {
    extern __shared__ float sm[];
    float* Wk  = sm;                       // [32][1028] (row gq, col k)
    float* h0s = sm + 32 * 1028;           // 1024
    float* h1s = h0s + 1024;               // 1024
    float* xq0 = h1s + 1024;               // 4096
    float* xq1 = xq0 + 4096;               // 4096
    float* qc0 = xq1 + 4096;               // 32 (16B aligned)
    float* qc1 = qc0 + 32;                 // 32

    const int tid  = threadIdx.x;
    const int warp = tid >> 5, lane = tid & 31;
    const int b0   = blockIdx.x * 2;

    // Wk[gq][k] = Wg[g][D + k][q]   (4096 (g,k) pairs, 8 gq-scatter each)
    #pragma unroll
    for (int it = 0; it < 8; it++) {
        int p = tid + it * 512;
        int g = p >> 10, k = p & 1023;
        const float* src = Wg + g * (2048 * 8) + (size_t)(1024 + k) * 8;
        float4 v0 = *(const float4*)src;
        float4 v1 = *(const float4*)(src + 4);
        float* dst = Wk + (g * 8) * 1028 + k;
        dst[0]        = v0.x; dst[1028]     = v0.y;
        dst[2 * 1028] = v0.z; dst[3 * 1028] = v0.w;
        dst[4 * 1028] = v1.x; dst[5 * 1028] = v1.y;
        dst[6 * 1028] = v1.z; dst[7 * 1028] = v1.w;
    }
    // xq[b][t][gq] = embproj[token][gq] + bg[gq] + theta[gq]
    #pragma unroll
    for (int it = 0; it < 16; it++) {
        int p  = tid + it * 512;
        int bb = p >> 12, r = p & 4095;
        int t  = r >> 5, gq = r & 31;
        int token = sentence[t * B_ + b0 + bb];
        (bb ? xq1 : xq0)[t * 32 + gq] =
            g_embproj[token * GQ + gq] + bg[gq] + theta[gq];
    }
    // per-thread Wp slices for j = tid and j = tid + 512
    float wpreg[64], bpv[8];
    #pragma unroll
    for (int k = 0; k < 32; k++) {
        wpreg[k]      = Wp[k * H_ + tid];
        wpreg[32 + k] = Wp[k * H_ + tid + 512];
    }
    #pragma unroll
    for (int g = 0; g < 4; g++) {
        bpv[g]     = bp[g * H_ + tid];
        bpv[4 + g] = bp[g * H_ + tid + 512];
    }

    h0s[tid] = 0.f; h0s[tid + 512] = 0.f;
    h1s[tid] = 0.f; h1s[tid + 512] = 0.f;
    float h0a = 0.f, h0b = 0.f, h1a = 0.f, h1b = 0.f;
    float c0a = 0.f, c0b = 0.f, c1a = 0.f, c1b = 0.f;
    __syncthreads();

    const int gq0 = warp, gq1 = warp + 16;
    const float4* w0r = (const float4*)(Wk + gq0 * 1028);
    const float4* w1r = (const float4*)(Wk + gq1 * 1028);
    const float4* h04 = (const float4*)h0s;
    const float4* h14 = (const float4*)h1s;

    for (int t = 0; t < T_; t++) {
        // matvec: lanes parallel over k; warp owns (gq0, gq1) x (b0, b1)
        float a00 = 0.f, a01 = 0.f, a10 = 0.f, a11 = 0.f;
        #pragma unroll
        for (int i = 0; i < 8; i++) {
            float4 hv0 = h04[lane + 32 * i];
            float4 hv1 = h14[lane + 32 * i];
            float4 wa  = w0r[lane + 32 * i];
            float4 wb  = w1r[lane + 32 * i];
            a00 = fmaf(hv0.x, wa.x, a00); a00 = fmaf(hv0.y, wa.y, a00);
            a00 = fmaf(hv0.z, wa.z, a00); a00 = fmaf(hv0.w, wa.w, a00);
            a01 = fmaf(hv0.x, wb.x, a01); a01 = fmaf(hv0.y, wb.y, a01);
            a01 = fmaf(hv0.z, wb.z, a01); a01 = fmaf(hv0.w, wb.w, a01);
            a10 = fmaf(hv1.x, wa.x, a10); a10 = fmaf(hv1.y, wa.y, a10);
            a10 = fmaf(hv1.z, wa.z, a10); a10 = fmaf(hv1.w, wa.w, a10);
            a11 = fmaf(hv1.x, wb.x, a11); a11 = fmaf(hv1.y, wb.y, a11);
            a11 = fmaf(hv1.z, wb.z, a11); a11 = fmaf(hv1.w, wb.w, a11);
        }
        #pragma unroll
        for (int off = 16; off > 0; off >>= 1) {
            a00 += __shfl_xor_sync(~0u, a00, off);
            a01 += __shfl_xor_sync(~0u, a01, off);
            a10 += __shfl_xor_sync(~0u, a10, off);
            a11 += __shfl_xor_sync(~0u, a11, off);
        }
        if (lane == 0) {
            qc0[gq0] = __cosf(a00 + xq0[t * 32 + gq0]);
            qc0[gq1] = __cosf(a01 + xq0[t * 32 + gq1]);
            qc1[gq0] = __cosf(a10 + xq1[t * 32 + gq0]);
            qc1[gq1] = __cosf(a11 + xq1[t * 32 + gq1]);
        }
        __syncthreads();

        const float4* q0 = (const float4*)qc0;
        const float4* q1 = (const float4*)qc1;
        gate_update(q0, wpreg,      bpv,     c0a, h0a);
        gate_update(q0, wpreg + 32, bpv + 4, c0b, h0b);
        gate_update(q1, wpreg,      bpv,     c1a, h1a);
        gate_update(q1, wpreg + 32, bpv + 4, c1b, h1b);

        size_t base = ((size_t)t * B_ + b0) * H_;
        g_lstm[base + tid]            = __float2bfloat16(h0a);
        g_lstm[base + tid + 512]      = __float2bfloat16(h0b);
        g_lstm[base + H_ + tid]       = __float2bfloat16(h1a);
        g_lstm[base + H_ + tid + 512] = __float2bfloat16(h1b);
        h0s[tid] = h0a; h0s[tid + 512] = h0b;
        h1s[tid] = h1a; h1s[tid + 512] = h1b;
        __syncthreads();
    }
}

// ---------------- K3: fused tag GEMM (bf16 WMMA, 8 warps, 64x64 tiles) ------
// block = one (t, 128-tag chunk): tile 256(b) x 128(tags), K = 1024, KT = 64,
// 2-stage cp.async double buffer. b_tag cancels in batch-axis log_softmax.
#define A_STG (256 * 72)     // halves per A stage (ld = 72)
#define B_STG (64 * 136)     // halves per B stage (ld = 136)
#define TAG_SMEM (256 * 136 * 4 + 512 * 4)   // epilogue tile dominates (aliases)

__global__ __launch_bounds__(256, 1) void tag_kernel(float* __restrict__ out) {
    extern __shared__ char smraw[];
    __nv_bfloat16* Asm = (__nv_bfloat16*)smraw;   // 2 stages 256x72
    __nv_bfloat16* Bsm = Asm + 2 * A_STG;         // 2 stages 64x136
    float* Osm = (float*)smraw;                   // 256 x 136 fp32 (alias)
    float* red = Osm + 256 * 136;

    const int tid = threadIdx.x;
    const int t   = blockIdx.y;
    const int c0  = blockIdx.x * 128;
    const int w   = tid >> 5;
    const int wy  = w >> 1;        // 0..3 -> 64-row block
    const int wx  = w & 1;         // 0..1 -> 64-col block

    wmma::fragment<wmma::accumulator, 16, 16, 16, float> acc[4][4];
    #pragma unroll
    for (int i = 0; i < 4; i++)
        #pragma unroll
        for (int j = 0; j < 4; j++) wmma::fill_fragment(acc[i][j], 0.f);

    auto issue_tile = [&](int kt) {
        int s  = kt & 1;
        int k0 = kt * 64;
        __nv_bfloat16* As = Asm + s * A_STG;
        __nv_bfloat16* Bs = Bsm + s * B_STG;
        #pragma unroll
        for (int i = 0; i < 8; i++) {             // A: 256x64 = 2048 cp16
            int e = tid + i * 256;
            int row = e >> 3, c8 = (e & 7) * 8;
            cp16(&As[row * 72 + c8],
                 &g_lstm[((size_t)t * B_ + row) * H_ + k0 + c8]);
        }
        #pragma unroll
        for (int i = 0; i < 4; i++) {             // B: 64x128 = 1024 cp16
            int e = tid + i * 256;
            int row = e >> 4, c8 = (e & 15) * 8;
            cp16(&Bs[row * 136 + c8],
                 &g_wtag[(size_t)(k0 + row) * TAGS_ + c0 + c8]);
        }
        asm volatile("cp.async.commit_group;\n" ::);
    };

    issue_tile(0);
    for (int kt = 0; kt < 16; kt++) {
        if (kt + 1 < 16) {
            issue_tile(kt + 1);
            asm volatile("cp.async.wait_group 1;\n" ::);
        } else {
            asm volatile("cp.async.wait_group 0;\n" ::);
        }
        __syncthreads();
        int s = kt & 1;
        const __nv_bfloat16* As = Asm + s * A_STG;
        const __nv_bfloat16* Bs = Bsm + s * B_STG;
        #pragma unroll
        for (int ks = 0; ks < 64; ks += 16) {
            wmma::fragment<wmma::matrix_a, 16, 16, 16, __nv_bfloat16, wmma::row_major> af[4];
            wmma::fragment<wmma::matrix_b, 16, 16, 16, __nv_bfloat16, wmma::row_major> bf[4];
            #pragma unroll
            for (int i = 0; i < 4; i++)
                wmma::load_matrix_sync(af[i], &As[(wy * 64 + i * 16) * 72 + ks], 72);
            #pragma unroll
            for (int j = 0; j < 4; j++)
                wmma::load_matrix_sync(bf[j], &Bs[ks * 136 + wx * 64 + j * 16], 136);
            #pragma unroll
            for (int i = 0; i < 4; i++)
                #pragma unroll
                for (int j = 0; j < 4; j++)
                    wmma::mma_sync(acc[i][j], af[i], bf[j], acc[i][j]);
        }
        __syncthreads();
    }

    // spill accumulators to smem tile (aliases stage buffers; final sync above)
    #pragma unroll
    for (int i = 0; i < 4; i++)
        #pragma unroll
        for (int j = 0; j < 4; j++)
            wmma::store_matrix_sync(&Osm[(wy * 64 + i * 16) * 136 + wx * 64 + j * 16],
                                    acc[i][j], 136, wmma::mem_row_major);
    __syncthreads();

    // log_softmax over the 256 rows (batch) per column (tag); 256 threads
    const int p = tid >> 7;        // 0..1, 128 rows each
    const int c = tid & 127;
    float m = -1e30f;
    #pragma unroll 8
    for (int i = 0; i < 128; i++) m = fmaxf(m, Osm[(p * 128 + i) * 136 + c]);
    red[p * 128 + c] = m;
    __syncthreads();
    float M = fmaxf(red[c], red[128 + c]);
    float ssum = 0.f;
    #pragma unroll 8
    for (int i = 0; i < 128; i++) ssum += __expf(Osm[(p * 128 + i) * 136 + c] - M);
    __syncthreads();
    red[p * 128 + c] = ssum;
    __syncthreads();
    float lse = M + logf(red[c] + red[128 + c]);
    #pragma unroll 8
    for (int i = 0; i < 128; i++) {
        int b = p * 128 + i;
        out[((size_t)t * B_ + b) * TAGS_ + c0 + c] = Osm[b * 136 + c] - lse;
    }
}

// ---------------- launch -----------------------------------------------------
extern "C" void kernel_launch(void* const* d_in, const int* in_sizes, int n_in,
                              void* d_out, int out_size) {
    const int*   sentence = (const int*)  d_in[0];
    const float* emb      = (const float*)d_in[1];
    const float* Wg       = (const float*)d_in[2];
    const float* bg       = (const float*)d_in[3];
    const float* theta    = (const float*)d_in[4];
    const float* Wp       = (const float*)d_in[5];
    const float* bp       = (const float*)d_in[6];
    const float* W_tag    = (const float*)d_in[7];
    // d_in[8] = b_tag: cancels in log_softmax over batch axis -> unused
    float* out = (float*)d_out;

    cudaFuncSetAttribute(lstm_kernel, cudaFuncAttributeMaxDynamicSharedMemorySize, LSTM_SMEM);
    cudaFuncSetAttribute(tag_kernel,  cudaFuncAttributeMaxDynamicSharedMemorySize, TAG_SMEM);

    wtag_convert<<<(H_ * TAGS_) / 256, 256>>>(W_tag);
    embproj_kernel<<<V_ / 128, 256>>>(emb, Wg);
    lstm_kernel<<<B_ / 2, 512, LSTM_SMEM>>>(sentence, Wg, bg, theta, Wp, bp);
    dim3 g3(TAGS_ / 128, T_);
    tag_kernel<<<g3, 256, TAG_SMEM>>>(out);
}